// round 15
// baseline (speedup 1.0000x reference)
#include <cuda_runtime.h>

#define NN 100000
#define NE 3200000
#define H  32

// Scratch (static device globals -- no allocation in kernel_launch).
__device__ float g_h[NN * H];       // node hidden state
__device__ float g_pa[NN * H];      // h @ msg_w1[:,0:32,:]
__device__ float g_pb[NN * H];      // h @ msg_w1[:,32:64,:] + msg_b1
__device__ float g_aggT[NN * H];    // segment-sum of post-relu msg hidden t
__device__ int   g_degi[NN];        // in-degree
__device__ int   g_start[NN];       // CSR row start
__device__ int   g_cursor[NN];      // scatter cursor
__device__ int   g_bsum[512];       // block sums for scan
__device__ int   g_csr_src[NE];     // src node per CSR slot
__device__ float4 g_csr_ef[NE];     // edge features permuted into CSR order
__device__ float g_W[2][H * H];     // msg_w2 @ upd_w1_b   (both rounds)
__device__ float g_c[2][H];         // msg_b2 @ upd_w1_b   (both rounds)
__device__ int   g_is64;            // 1 if edge buffer holds int64 pairs

// ---------------------------------------------------------------- dtype probe
__global__ void k_detect(const int* __restrict__ edges_i32, int ne) {
    int t = threadIdx.x;
    int nonzero = 0;
    for (int i = t; i < 256; i += 32) {
        long long idx = 2LL * i + 1;
        if (idx < 2LL * (long long)ne) nonzero |= (edges_i32[idx] != 0);
    }
#pragma unroll
    for (int off = 16; off > 0; off >>= 1)
        nonzero |= __shfl_xor_sync(0xFFFFFFFFu, nonzero, off);
    if (t == 0) g_is64 = nonzero ? 0 : 1;
}

__device__ __forceinline__ void load_edge(const void* edges, int e, int& s, int& d, int is64) {
    if (is64) {
        longlong2 ed = reinterpret_cast<const longlong2*>(edges)[e];
        s = (int)ed.x; d = (int)ed.y;
    } else {
        int2 ed = reinterpret_cast<const int2*>(edges)[e];
        s = ed.x; d = ed.y;
    }
}

// ---------------------------------------------------------------- encoder + pre(round 0)
__global__ void k_enc(const float* __restrict__ nf,
                      const float* __restrict__ w1, const float* __restrict__ b1,
                      const float* __restrict__ w2, const float* __restrict__ b2,
                      const float* __restrict__ msg_w1, const float* __restrict__ msg_b1,
                      int n) {
    __shared__ float sw1[16 * H], sw2[H * H], sMA[H * H], sMB[H * H];
    __shared__ float sb1[H], sb2[H], smb1[H];
    int t = threadIdx.x;
    for (int i = t; i < 16 * H; i += blockDim.x) sw1[i] = w1[i];
    for (int i = t; i < H * H;  i += blockDim.x) {
        sw2[i] = w2[i];
        sMA[i] = msg_w1[i];
        sMB[i] = msg_w1[H * H + i];
    }
    if (t < H) { sb1[t] = b1[t]; sb2[t] = b2[t]; smb1[t] = msg_b1[t]; }
    __syncthreads();
    int n0 = blockIdx.x * blockDim.x + t;
    if (n0 >= n) return;

    const float4* x4 = reinterpret_cast<const float4*>(nf + (size_t)n0 * 16);
    float x[16];
#pragma unroll
    for (int i = 0; i < 4; i++) {
        float4 v = x4[i];
        x[4*i] = v.x; x[4*i+1] = v.y; x[4*i+2] = v.z; x[4*i+3] = v.w;
    }
    float a[H];
#pragma unroll
    for (int j = 0; j < H; j++) a[j] = sb1[j];
#pragma unroll
    for (int k = 0; k < 16; k++) {
        float xv = x[k];
#pragma unroll
        for (int j = 0; j < H; j++) a[j] = fmaf(xv, sw1[k * H + j], a[j]);
    }
#pragma unroll
    for (int j = 0; j < H; j++) a[j] = fmaxf(a[j], 0.f);
    float o[H];
#pragma unroll
    for (int j = 0; j < H; j++) o[j] = sb2[j];
#pragma unroll
    for (int k = 0; k < H; k++) {
        float av = a[k];
#pragma unroll
        for (int j = 0; j < H; j++) o[j] = fmaf(av, sw2[k * H + j], o[j]);
    }
    float4* hv = reinterpret_cast<float4*>(g_h + (size_t)n0 * H);
#pragma unroll
    for (int i = 0; i < 8; i++) hv[i] = make_float4(o[4*i], o[4*i+1], o[4*i+2], o[4*i+3]);

    float pa[H];
#pragma unroll
    for (int j = 0; j < H; j++) pa[j] = 0.f;
#pragma unroll
    for (int k = 0; k < H; k++) {
        float hv2 = o[k];
#pragma unroll
        for (int j = 0; j < H; j++) pa[j] = fmaf(hv2, sMA[k * H + j], pa[j]);
    }
    float4* pav = reinterpret_cast<float4*>(g_pa + (size_t)n0 * H);
#pragma unroll
    for (int i = 0; i < 8; i++) pav[i] = make_float4(pa[4*i], pa[4*i+1], pa[4*i+2], pa[4*i+3]);

    float pb[H];
#pragma unroll
    for (int j = 0; j < H; j++) pb[j] = smb1[j];
#pragma unroll
    for (int k = 0; k < H; k++) {
        float hv2 = o[k];
#pragma unroll
        for (int j = 0; j < H; j++) pb[j] = fmaf(hv2, sMB[k * H + j], pb[j]);
    }
    float4* pbv = reinterpret_cast<float4*>(g_pb + (size_t)n0 * H);
#pragma unroll
    for (int i = 0; i < 8; i++) pbv[i] = make_float4(pb[4*i], pb[4*i+1], pb[4*i+2], pb[4*i+3]);

    g_degi[n0] = 0;
}

// ---------------------------------------------------------------- degree count
__global__ void k_deg(const void* __restrict__ edges, int ne, int n) {
    int e = blockIdx.x * blockDim.x + threadIdx.x;
    if (e >= ne) return;
    int is64 = g_is64;
    int s, d;
    load_edge(edges, e, s, d, is64);
    if ((unsigned)d < (unsigned)n) atomicAdd(&g_degi[d], 1);
}

// ---------------------------------------------------------------- prefix scan
__global__ void k_scan1(int n) {
    __shared__ int sh[256];
    int i = blockIdx.x * 256 + threadIdx.x;
    int v = (i < n) ? g_degi[i] : 0;
    sh[threadIdx.x] = v;
    __syncthreads();
#pragma unroll
    for (int off = 1; off < 256; off <<= 1) {
        int t = (threadIdx.x >= off) ? sh[threadIdx.x - off] : 0;
        __syncthreads();
        sh[threadIdx.x] += t;
        __syncthreads();
    }
    if (i < n) g_start[i] = sh[threadIdx.x] - v;
    if (threadIdx.x == 255) g_bsum[blockIdx.x] = sh[255];
}

__global__ void k_scan2(int nb) {
    __shared__ int sh[512];
    int v = (threadIdx.x < nb) ? g_bsum[threadIdx.x] : 0;
    sh[threadIdx.x] = v;
    __syncthreads();
#pragma unroll
    for (int off = 1; off < 512; off <<= 1) {
        int t = (threadIdx.x >= off) ? sh[threadIdx.x - off] : 0;
        __syncthreads();
        sh[threadIdx.x] += t;
        __syncthreads();
    }
    if (threadIdx.x < nb) g_bsum[threadIdx.x] = sh[threadIdx.x] - v;
}

__global__ void k_scan3(int n) {
    int i = blockIdx.x * blockDim.x + threadIdx.x;
    if (i >= n) return;
    int st = g_start[i] + g_bsum[i >> 8];
    g_start[i]  = st;
    g_cursor[i] = st;
}

// ---------------------------------------------------------------- CSR scatter
__global__ void k_scatter(const void* __restrict__ edges,
                          const float* __restrict__ ef, int ne, int n) {
    int e = blockIdx.x * blockDim.x + threadIdx.x;
    if (e >= ne) return;
    int is64 = g_is64;
    int s, d;
    load_edge(edges, e, s, d, is64);
    if ((unsigned)s >= (unsigned)n || (unsigned)d >= (unsigned)n) return;
    int pos = atomicAdd(&g_cursor[d], 1);
    if ((unsigned)pos < (unsigned)ne) {
        g_csr_src[pos] = s;
        g_csr_ef[pos]  = reinterpret_cast<const float4*>(ef)[e];
    }
}

// ---------------------------------------------------------------- fused weights, both rounds
__global__ void k_combine(const float* __restrict__ msg_w2,
                          const float* __restrict__ msg_b2,
                          const float* __restrict__ upd_w1) {
    int r = blockIdx.x;
    const float* w2  = msg_w2 + (size_t)r * H * H;
    const float* u1b = upd_w1 + (size_t)r * 2 * H * H + H * H;
    int j = threadIdx.x, i = threadIdx.y;
    float s = 0.f;
#pragma unroll
    for (int k = 0; k < H; k++) s = fmaf(w2[i * H + k], u1b[k * H + j], s);
    g_W[r][i * H + j] = s;
    if (i == 0) {
        const float* b2 = msg_b2 + (size_t)r * H;
        float c = 0.f;
#pragma unroll
        for (int k = 0; k < H; k++) c = fmaf(b2[k], u1b[k * H + j], c);
        g_c[r][j] = c;
    }
}

// ---------------------------------------------------------------- CSR aggregation (hot)
// Warp-per-node, lane j owns column j. Edge metadata staged coalesced into
// smem (2 LDG per 32 edges instead of 64), read back via LDS broadcast.
__global__ __launch_bounds__(256)
void k_agg(const float* __restrict__ msg_w1, int r, int n) {
    __shared__ int    s_src[8][32];
    __shared__ float4 s_ef [8][32];
    int wid  = threadIdx.x >> 5;
    int lane = threadIdx.x & 31;
    int gw   = blockIdx.x * 8 + wid;
    if (gw >= n) return;

    const float* wc = msg_w1 + (size_t)r * 68 * H + 64 * H;
    float wc0 = __ldg(wc + 0 * H + lane);
    float wc1 = __ldg(wc + 1 * H + lane);
    float wc2 = __ldg(wc + 2 * H + lane);
    float wc3 = __ldg(wc + 3 * H + lane);

    float pbv = g_pb[(size_t)gw * H + lane];
    int st  = g_start[gw];
    int deg = g_degi[gw];

    float acc = 0.f;
    for (int base = 0; base < deg; base += 32) {
        int m = deg - base; if (m > 32) m = 32;
        if (lane < m) {
            int idx = st + base + lane;
            s_src[wid][lane] = __ldg(&g_csr_src[idx]);   // coalesced
            s_ef [wid][lane] = __ldg(&g_csr_ef[idx]);    // coalesced
        }
        __syncwarp();
        int u = 0;
        for (; u + 8 <= m; u += 8) {
            int s[8];
#pragma unroll
            for (int q = 0; q < 8; q++) s[q] = s_src[wid][u + q];     // LDS broadcast
            float p[8];
#pragma unroll
            for (int q = 0; q < 8; q++) p[q] = __ldg(&g_pa[(size_t)s[q] * H + lane]);
#pragma unroll
            for (int q = 0; q < 8; q++) {
                float4 f = s_ef[wid][u + q];                           // LDS.128 broadcast
                acc += fmaxf(p[q] + pbv + f.x * wc0 + f.y * wc1
                                        + f.z * wc2 + f.w * wc3, 0.f);
            }
        }
        for (; u < m; u++) {
            int    s = s_src[wid][u];
            float  p = __ldg(&g_pa[(size_t)s * H + lane]);
            float4 f = s_ef[wid][u];
            acc += fmaxf(p + pbv + f.x * wc0 + f.y * wc1 + f.z * wc2 + f.w * wc3, 0.f);
        }
        __syncwarp();
    }
    g_aggT[(size_t)gw * H + lane] = acc;
}

// ---------------------------------------------------------------- node update (round 0) + pre(round 1)
__global__ __launch_bounds__(256)
void k_upd_mid(const float* __restrict__ uw1, const float* __restrict__ ub1,
               const float* __restrict__ uw2, const float* __restrict__ ub2,
               const float* __restrict__ msg_w1, const float* __restrict__ msg_b1,
               int n) {
    const int r = 0;
    __shared__ float sA[H * H], sW[H * H], sU[H * H], sMA[H * H], sMB[H * H];
    __shared__ float s_b1[H], s_b2[H], s_c[H], smb1[H];
    const float* u1a = uw1 + (size_t)r * 2 * H * H;
    const float* mw  = msg_w1 + (size_t)(r + 1) * 68 * H;
    int t = threadIdx.x;
    for (int i = t; i < H * H; i += blockDim.x) {
        sA[i]  = u1a[i];
        sW[i]  = g_W[r][i];
        sU[i]  = uw2[(size_t)r * H * H + i];
        sMA[i] = mw[i];
        sMB[i] = mw[H * H + i];
    }
    if (t < H) {
        s_b1[t] = ub1[(size_t)r * H + t];
        s_b2[t] = ub2[(size_t)r * H + t];
        s_c[t]  = g_c[r][t];
        smb1[t] = msg_b1[(size_t)(r + 1) * H + t];
    }
    __syncthreads();
    int n0 = blockIdx.x * blockDim.x + t;
    if (n0 >= n) return;

    float h[H], ag[H];
    const float4* h4 = reinterpret_cast<const float4*>(g_h    + (size_t)n0 * H);
    const float4* a4 = reinterpret_cast<const float4*>(g_aggT + (size_t)n0 * H);
#pragma unroll
    for (int i = 0; i < 8; i++) {
        float4 v = h4[i]; h[4*i] = v.x; h[4*i+1] = v.y; h[4*i+2] = v.z; h[4*i+3] = v.w;
        float4 w = a4[i]; ag[4*i] = w.x; ag[4*i+1] = w.y; ag[4*i+2] = w.z; ag[4*i+3] = w.w;
    }
    float deg = (float)g_degi[n0];
    float s[H];
#pragma unroll
    for (int j = 0; j < H; j++) s[j] = fmaf(deg, s_c[j], s_b1[j]);
#pragma unroll
    for (int k = 0; k < H; k++) {
        float hv = h[k], av = ag[k];
#pragma unroll
        for (int j = 0; j < H; j++) {
            s[j] = fmaf(hv, sA[k * H + j], s[j]);
            s[j] = fmaf(av, sW[k * H + j], s[j]);
        }
    }
#pragma unroll
    for (int j = 0; j < H; j++) s[j] = fmaxf(s[j], 0.f);
    float o[H];
#pragma unroll
    for (int j = 0; j < H; j++) o[j] = h[j] + s_b2[j];
#pragma unroll
    for (int k = 0; k < H; k++) {
        float tv = s[k];
#pragma unroll
        for (int j = 0; j < H; j++) o[j] = fmaf(tv, sU[k * H + j], o[j]);
    }
    float4* hv = reinterpret_cast<float4*>(g_h + (size_t)n0 * H);
#pragma unroll
    for (int i = 0; i < 8; i++) hv[i] = make_float4(o[4*i], o[4*i+1], o[4*i+2], o[4*i+3]);

    float pa[H];
#pragma unroll
    for (int j = 0; j < H; j++) pa[j] = 0.f;
#pragma unroll
    for (int k = 0; k < H; k++) {
        float hv2 = o[k];
#pragma unroll
        for (int j = 0; j < H; j++) pa[j] = fmaf(hv2, sMA[k * H + j], pa[j]);
    }
    float4* pav = reinterpret_cast<float4*>(g_pa + (size_t)n0 * H);
#pragma unroll
    for (int i = 0; i < 8; i++) pav[i] = make_float4(pa[4*i], pa[4*i+1], pa[4*i+2], pa[4*i+3]);

    float pb[H];
#pragma unroll
    for (int j = 0; j < H; j++) pb[j] = smb1[j];
#pragma unroll
    for (int k = 0; k < H; k++) {
        float hv2 = o[k];
#pragma unroll
        for (int j = 0; j < H; j++) pb[j] = fmaf(hv2, sMB[k * H + j], pb[j]);
    }
    float4* pbv = reinterpret_cast<float4*>(g_pb + (size_t)n0 * H);
#pragma unroll
    for (int i = 0; i < 8; i++) pbv[i] = make_float4(pb[4*i], pb[4*i+1], pb[4*i+2], pb[4*i+3]);
}

// ---------------------------------------------------------------- node update (round 1) + head
__global__ __launch_bounds__(256)
void k_upd_last(const float* __restrict__ uw1, const float* __restrict__ ub1,
                const float* __restrict__ uw2, const float* __restrict__ ub2,
                const float* __restrict__ hw1, const float* __restrict__ hb1,
                const float* __restrict__ hw2, const float* __restrict__ hb2,
                float* __restrict__ out, int n) {
    const int r = 1;
    __shared__ float sA[H * H], sW[H * H], sU[H * H], sHW[H * H];
    __shared__ float s_b1[H], s_b2[H], s_c[H], shb1[H], shw2[H];
    const float* u1a = uw1 + (size_t)r * 2 * H * H;
    int t = threadIdx.x;
    for (int i = t; i < H * H; i += blockDim.x) {
        sA[i]  = u1a[i];
        sW[i]  = g_W[r][i];
        sU[i]  = uw2[(size_t)r * H * H + i];
        sHW[i] = hw1[i];
    }
    if (t < H) {
        s_b1[t] = ub1[(size_t)r * H + t];
        s_b2[t] = ub2[(size_t)r * H + t];
        s_c[t]  = g_c[r][t];
        shb1[t] = hb1[t];
        shw2[t] = hw2[t];
    }
    __syncthreads();
    int n0 = blockIdx.x * blockDim.x + t;
    if (n0 >= n) return;

    float h[H], ag[H];
    const float4* h4 = reinterpret_cast<const float4*>(g_h    + (size_t)n0 * H);
    const float4* a4 = reinterpret_cast<const float4*>(g_aggT + (size_t)n0 * H);
#pragma unroll
    for (int i = 0; i < 8; i++) {
        float4 v = h4[i]; h[4*i] = v.x; h[4*i+1] = v.y; h[4*i+2] = v.z; h[4*i+3] = v.w;
        float4 w = a4[i]; ag[4*i] = w.x; ag[4*i+1] = w.y; ag[4*i+2] = w.z; ag[4*i+3] = w.w;
    }
    float deg = (float)g_degi[n0];
    float s[H];
#pragma unroll
    for (int j = 0; j < H; j++) s[j] = fmaf(deg, s_c[j], s_b1[j]);
#pragma unroll
    for (int k = 0; k < H; k++) {
        float hv = h[k], av = ag[k];
#pragma unroll
        for (int j = 0; j < H; j++) {
            s[j] = fmaf(hv, sA[k * H + j], s[j]);
            s[j] = fmaf(av, sW[k * H + j], s[j]);
        }
    }
#pragma unroll
    for (int j = 0; j < H; j++) s[j] = fmaxf(s[j], 0.f);
    float o[H];
#pragma unroll
    for (int j = 0; j < H; j++) o[j] = h[j] + s_b2[j];
#pragma unroll
    for (int k = 0; k < H; k++) {
        float tv = s[k];
#pragma unroll
        for (int j = 0; j < H; j++) o[j] = fmaf(tv, sU[k * H + j], o[j]);
    }

    float a[H];
#pragma unroll
    for (int j = 0; j < H; j++) a[j] = shb1[j];
#pragma unroll
    for (int k = 0; k < H; k++) {
        float hv2 = o[k];
#pragma unroll
        for (int j = 0; j < H; j++) a[j] = fmaf(hv2, sHW[k * H + j], a[j]);
    }
    float res = hb2[0];
#pragma unroll
    for (int j = 0; j < H; j++) res = fmaf(fmaxf(a[j], 0.f), shw2[j], res);
    out[n0] = res;
}

// ---------------------------------------------------------------- launch
extern "C" void kernel_launch(void* const* d_in, const int* in_sizes, int n_in,
                              void* d_out, int out_size) {
    const float* nf      = (const float*)d_in[0];
    const void*  edges   = d_in[1];
    const float* ef      = (const float*)d_in[2];
    const float* enc_w1  = (const float*)d_in[3];
    const float* enc_b1  = (const float*)d_in[4];
    const float* enc_w2  = (const float*)d_in[5];
    const float* enc_b2  = (const float*)d_in[6];
    const float* msg_w1  = (const float*)d_in[7];
    const float* msg_b1  = (const float*)d_in[8];
    const float* msg_w2  = (const float*)d_in[9];
    const float* msg_b2  = (const float*)d_in[10];
    const float* upd_w1  = (const float*)d_in[11];
    const float* upd_b1  = (const float*)d_in[12];
    const float* upd_w2  = (const float*)d_in[13];
    const float* upd_b2  = (const float*)d_in[14];
    const float* head_w1 = (const float*)d_in[15];
    const float* head_b1 = (const float*)d_in[16];
    const float* head_w2 = (const float*)d_in[17];
    const float* head_b2 = (const float*)d_in[18];

    int n  = in_sizes[0] / 16;  // 100000
    int ne = in_sizes[1] / 2;   // 3200000
    if (n > NN) n = NN;
    if (ne > NE) ne = NE;

    int nb = (n + 255) / 256;
    int eb = (ne + 255) / 256;
    int ab = (n + 7) / 8;               // k_agg: 8 warps (nodes) per block

    k_detect<<<1, 32>>>((const int*)edges, ne);
    k_enc<<<nb, 256>>>(nf, enc_w1, enc_b1, enc_w2, enc_b2, msg_w1, msg_b1, n);
    k_deg<<<eb, 256>>>(edges, ne, n);
    k_scan1<<<nb, 256>>>(n);
    k_scan2<<<1, 512>>>(nb);
    k_scan3<<<nb, 256>>>(n);
    k_scatter<<<eb, 256>>>(edges, ef, ne, n);
    k_combine<<<2, dim3(32, 32)>>>(msg_w2, msg_b2, upd_w1);
    k_agg<<<ab, 256>>>(msg_w1, 0, n);
    k_upd_mid<<<nb, 256>>>(upd_w1, upd_b1, upd_w2, upd_b2, msg_w1, msg_b1, n);
    k_agg<<<ab, 256>>>(msg_w1, 1, n);
    k_upd_last<<<nb, 256>>>(upd_w1, upd_b1, upd_w2, upd_b2,
                            head_w1, head_b1, head_w2, head_b2, (float*)d_out, n);
}

// round 17
// speedup vs baseline: 1.1298x; 1.1298x over previous
#include <cuda_runtime.h>

#define NN 100000
#define NE 3200000
#define H  32

// Scratch (static device globals -- no allocation in kernel_launch).
__device__ float g_h[NN * H];       // node hidden state
__device__ float g_pa[NN * H];      // h @ msg_w1[:,0:32,:]
__device__ float g_pb[NN * H];      // h @ msg_w1[:,32:64,:] + msg_b1
__device__ float g_aggT[NN * H];    // segment-sum of post-relu msg hidden t
__device__ int   g_degi[NN];        // in-degree
__device__ int   g_start[NN];       // CSR row start
__device__ int   g_cursor[NN];      // scatter cursor
__device__ int   g_bsum[512];       // block sums for scan
__device__ int   g_csr_src[NE];     // src node per CSR slot
__device__ float4 g_csr_ef[NE];     // edge features permuted into CSR order
__device__ float g_W[2][H * H];     // msg_w2 @ upd_w1_b   (both rounds)
__device__ float g_c[2][H];         // msg_b2 @ upd_w1_b   (both rounds)
__device__ int   g_is64;            // 1 if edge buffer holds int64 pairs

// ---------------------------------------------------------------- dtype probe
__global__ void k_detect(const int* __restrict__ edges_i32, int ne) {
    int t = threadIdx.x;
    int nonzero = 0;
    for (int i = t; i < 256; i += 32) {
        long long idx = 2LL * i + 1;
        if (idx < 2LL * (long long)ne) nonzero |= (edges_i32[idx] != 0);
    }
#pragma unroll
    for (int off = 16; off > 0; off >>= 1)
        nonzero |= __shfl_xor_sync(0xFFFFFFFFu, nonzero, off);
    if (t == 0) g_is64 = nonzero ? 0 : 1;
}

__device__ __forceinline__ void load_edge(const void* edges, int e, int& s, int& d, int is64) {
    if (is64) {
        longlong2 ed = reinterpret_cast<const longlong2*>(edges)[e];
        s = (int)ed.x; d = (int)ed.y;
    } else {
        int2 ed = reinterpret_cast<const int2*>(edges)[e];
        s = ed.x; d = ed.y;
    }
}

// ---------------------------------------------------------------- encoder + pre(round 0)
__global__ void k_enc(const float* __restrict__ nf,
                      const float* __restrict__ w1, const float* __restrict__ b1,
                      const float* __restrict__ w2, const float* __restrict__ b2,
                      const float* __restrict__ msg_w1, const float* __restrict__ msg_b1,
                      int n) {
    __shared__ float sw1[16 * H], sw2[H * H], sMA[H * H], sMB[H * H];
    __shared__ float sb1[H], sb2[H], smb1[H];
    int t = threadIdx.x;
    for (int i = t; i < 16 * H; i += blockDim.x) sw1[i] = w1[i];
    for (int i = t; i < H * H;  i += blockDim.x) {
        sw2[i] = w2[i];
        sMA[i] = msg_w1[i];
        sMB[i] = msg_w1[H * H + i];
    }
    if (t < H) { sb1[t] = b1[t]; sb2[t] = b2[t]; smb1[t] = msg_b1[t]; }
    __syncthreads();
    int n0 = blockIdx.x * blockDim.x + t;
    if (n0 >= n) return;

    const float4* x4 = reinterpret_cast<const float4*>(nf + (size_t)n0 * 16);
    float x[16];
#pragma unroll
    for (int i = 0; i < 4; i++) {
        float4 v = x4[i];
        x[4*i] = v.x; x[4*i+1] = v.y; x[4*i+2] = v.z; x[4*i+3] = v.w;
    }
    float a[H];
#pragma unroll
    for (int j = 0; j < H; j++) a[j] = sb1[j];
#pragma unroll
    for (int k = 0; k < 16; k++) {
        float xv = x[k];
#pragma unroll
        for (int j = 0; j < H; j++) a[j] = fmaf(xv, sw1[k * H + j], a[j]);
    }
#pragma unroll
    for (int j = 0; j < H; j++) a[j] = fmaxf(a[j], 0.f);
    float o[H];
#pragma unroll
    for (int j = 0; j < H; j++) o[j] = sb2[j];
#pragma unroll
    for (int k = 0; k < H; k++) {
        float av = a[k];
#pragma unroll
        for (int j = 0; j < H; j++) o[j] = fmaf(av, sw2[k * H + j], o[j]);
    }
    float4* hv = reinterpret_cast<float4*>(g_h + (size_t)n0 * H);
#pragma unroll
    for (int i = 0; i < 8; i++) hv[i] = make_float4(o[4*i], o[4*i+1], o[4*i+2], o[4*i+3]);

    float pa[H];
#pragma unroll
    for (int j = 0; j < H; j++) pa[j] = 0.f;
#pragma unroll
    for (int k = 0; k < H; k++) {
        float hv2 = o[k];
#pragma unroll
        for (int j = 0; j < H; j++) pa[j] = fmaf(hv2, sMA[k * H + j], pa[j]);
    }
    float4* pav = reinterpret_cast<float4*>(g_pa + (size_t)n0 * H);
#pragma unroll
    for (int i = 0; i < 8; i++) pav[i] = make_float4(pa[4*i], pa[4*i+1], pa[4*i+2], pa[4*i+3]);

    float pb[H];
#pragma unroll
    for (int j = 0; j < H; j++) pb[j] = smb1[j];
#pragma unroll
    for (int k = 0; k < H; k++) {
        float hv2 = o[k];
#pragma unroll
        for (int j = 0; j < H; j++) pb[j] = fmaf(hv2, sMB[k * H + j], pb[j]);
    }
    float4* pbv = reinterpret_cast<float4*>(g_pb + (size_t)n0 * H);
#pragma unroll
    for (int i = 0; i < 8; i++) pbv[i] = make_float4(pb[4*i], pb[4*i+1], pb[4*i+2], pb[4*i+3]);

    g_degi[n0] = 0;
}

// ---------------------------------------------------------------- degree count
__global__ void k_deg(const void* __restrict__ edges, int ne, int n) {
    int e = blockIdx.x * blockDim.x + threadIdx.x;
    if (e >= ne) return;
    int is64 = g_is64;
    int s, d;
    load_edge(edges, e, s, d, is64);
    if ((unsigned)d < (unsigned)n) atomicAdd(&g_degi[d], 1);
}

// ---------------------------------------------------------------- prefix scan
__global__ void k_scan1(int n) {
    __shared__ int sh[256];
    int i = blockIdx.x * 256 + threadIdx.x;
    int v = (i < n) ? g_degi[i] : 0;
    sh[threadIdx.x] = v;
    __syncthreads();
#pragma unroll
    for (int off = 1; off < 256; off <<= 1) {
        int t = (threadIdx.x >= off) ? sh[threadIdx.x - off] : 0;
        __syncthreads();
        sh[threadIdx.x] += t;
        __syncthreads();
    }
    if (i < n) g_start[i] = sh[threadIdx.x] - v;
    if (threadIdx.x == 255) g_bsum[blockIdx.x] = sh[255];
}

__global__ void k_scan2(int nb) {
    __shared__ int sh[512];
    int v = (threadIdx.x < nb) ? g_bsum[threadIdx.x] : 0;
    sh[threadIdx.x] = v;
    __syncthreads();
#pragma unroll
    for (int off = 1; off < 512; off <<= 1) {
        int t = (threadIdx.x >= off) ? sh[threadIdx.x - off] : 0;
        __syncthreads();
        sh[threadIdx.x] += t;
        __syncthreads();
    }
    if (threadIdx.x < nb) g_bsum[threadIdx.x] = sh[threadIdx.x] - v;
}

__global__ void k_scan3(int n) {
    int i = blockIdx.x * blockDim.x + threadIdx.x;
    if (i >= n) return;
    int st = g_start[i] + g_bsum[i >> 8];
    g_start[i]  = st;
    g_cursor[i] = st;
}

// ---------------------------------------------------------------- CSR scatter
__global__ void k_scatter(const void* __restrict__ edges,
                          const float* __restrict__ ef, int ne, int n) {
    int e = blockIdx.x * blockDim.x + threadIdx.x;
    if (e >= ne) return;
    int is64 = g_is64;
    int s, d;
    load_edge(edges, e, s, d, is64);
    if ((unsigned)s >= (unsigned)n || (unsigned)d >= (unsigned)n) return;
    int pos = atomicAdd(&g_cursor[d], 1);
    if ((unsigned)pos < (unsigned)ne) {
        g_csr_src[pos] = s;
        g_csr_ef[pos]  = reinterpret_cast<const float4*>(ef)[e];
    }
}

// ---------------------------------------------------------------- fused weights, both rounds
__global__ void k_combine(const float* __restrict__ msg_w2,
                          const float* __restrict__ msg_b2,
                          const float* __restrict__ upd_w1) {
    int r = blockIdx.x;
    const float* w2  = msg_w2 + (size_t)r * H * H;
    const float* u1b = upd_w1 + (size_t)r * 2 * H * H + H * H;
    int j = threadIdx.x, i = threadIdx.y;
    float s = 0.f;
#pragma unroll
    for (int k = 0; k < H; k++) s = fmaf(w2[i * H + k], u1b[k * H + j], s);
    g_W[r][i * H + j] = s;
    if (i == 0) {
        const float* b2 = msg_b2 + (size_t)r * H;
        float c = 0.f;
#pragma unroll
        for (int k = 0; k < H; k++) c = fmaf(b2[k], u1b[k * H + j], c);
        g_c[r][j] = c;
    }
}

// ---------------------------------------------------------------- CSR aggregation (hot)
// Half-warp per node: lanes 0-15 -> node 2g, lanes 16-31 -> node 2g+1.
// Each lane owns 2 feature columns (float2). Per edge-pair the warp issues
// one src LDG (2 uniform addrs), one ef LDG.128 (2 uniform addrs), one pa
// LDG.64 (two 128B rows) => 1.5 LDG/edge vs 3 in the 1-node/warp layout.
__global__ __launch_bounds__(256)
void k_agg(const float* __restrict__ msg_w1, int r, int n) {
    int gw   = (blockIdx.x * blockDim.x + threadIdx.x) >> 5;  // warp id
    int lane = threadIdx.x & 31;
    int half = lane >> 4;          // which node of the pair
    int hl   = lane & 15;          // lane within half: owns cols 2*hl, 2*hl+1
    int node = gw * 2 + half;
    bool valid = node < n;
    int nd = valid ? node : 0;

    const float* wc = msg_w1 + (size_t)r * 68 * H + 64 * H;
    float2 w0 = *reinterpret_cast<const float2*>(wc + 0 * H + 2 * hl);
    float2 w1 = *reinterpret_cast<const float2*>(wc + 1 * H + 2 * hl);
    float2 w2 = *reinterpret_cast<const float2*>(wc + 2 * H + 2 * hl);
    float2 w3 = *reinterpret_cast<const float2*>(wc + 3 * H + 2 * hl);

    float2 pb2 = *reinterpret_cast<const float2*>(g_pb + (size_t)nd * H + 2 * hl);
    int st  = g_start[nd];
    int deg = valid ? g_degi[nd] : 0;

    float acc0 = 0.f, acc1 = 0.f;
    int k = 0;
    for (; k + 4 <= deg; k += 4) {
        int s[4];
#pragma unroll
        for (int q = 0; q < 4; q++) s[q] = __ldg(&g_csr_src[st + k + q]);
        float4 f[4];
#pragma unroll
        for (int q = 0; q < 4; q++) f[q] = __ldg(&g_csr_ef[st + k + q]);
        float2 p[4];
#pragma unroll
        for (int q = 0; q < 4; q++)
            p[q] = __ldg(reinterpret_cast<const float2*>(g_pa + (size_t)s[q] * H + 2 * hl));
#pragma unroll
        for (int q = 0; q < 4; q++) {
            float t0 = p[q].x + pb2.x + f[q].x * w0.x + f[q].y * w1.x
                                      + f[q].z * w2.x + f[q].w * w3.x;
            float t1 = p[q].y + pb2.y + f[q].x * w0.y + f[q].y * w1.y
                                      + f[q].z * w2.y + f[q].w * w3.y;
            acc0 += fmaxf(t0, 0.f);
            acc1 += fmaxf(t1, 0.f);
        }
    }
    for (; k < deg; k++) {
        int    s = __ldg(&g_csr_src[st + k]);
        float4 f = __ldg(&g_csr_ef[st + k]);
        float2 p = __ldg(reinterpret_cast<const float2*>(g_pa + (size_t)s * H + 2 * hl));
        float t0 = p.x + pb2.x + f.x * w0.x + f.y * w1.x + f.z * w2.x + f.w * w3.x;
        float t1 = p.y + pb2.y + f.x * w0.y + f.y * w1.y + f.z * w2.y + f.w * w3.y;
        acc0 += fmaxf(t0, 0.f);
        acc1 += fmaxf(t1, 0.f);
    }
    if (valid)
        *reinterpret_cast<float2*>(g_aggT + (size_t)node * H + 2 * hl) =
            make_float2(acc0, acc1);
}

// ---------------------------------------------------------------- node update (round 0) + pre(round 1)
__global__ __launch_bounds__(256)
void k_upd_mid(const float* __restrict__ uw1, const float* __restrict__ ub1,
               const float* __restrict__ uw2, const float* __restrict__ ub2,
               const float* __restrict__ msg_w1, const float* __restrict__ msg_b1,
               int n) {
    const int r = 0;
    __shared__ float sA[H * H], sW[H * H], sU[H * H], sMA[H * H], sMB[H * H];
    __shared__ float s_b1[H], s_b2[H], s_c[H], smb1[H];
    const float* u1a = uw1 + (size_t)r * 2 * H * H;
    const float* mw  = msg_w1 + (size_t)(r + 1) * 68 * H;
    int t = threadIdx.x;
    for (int i = t; i < H * H; i += blockDim.x) {
        sA[i]  = u1a[i];
        sW[i]  = g_W[r][i];
        sU[i]  = uw2[(size_t)r * H * H + i];
        sMA[i] = mw[i];
        sMB[i] = mw[H * H + i];
    }
    if (t < H) {
        s_b1[t] = ub1[(size_t)r * H + t];
        s_b2[t] = ub2[(size_t)r * H + t];
        s_c[t]  = g_c[r][t];
        smb1[t] = msg_b1[(size_t)(r + 1) * H + t];
    }
    __syncthreads();
    int n0 = blockIdx.x * blockDim.x + t;
    if (n0 >= n) return;

    float h[H], ag[H];
    const float4* h4 = reinterpret_cast<const float4*>(g_h    + (size_t)n0 * H);
    const float4* a4 = reinterpret_cast<const float4*>(g_aggT + (size_t)n0 * H);
#pragma unroll
    for (int i = 0; i < 8; i++) {
        float4 v = h4[i]; h[4*i] = v.x; h[4*i+1] = v.y; h[4*i+2] = v.z; h[4*i+3] = v.w;
        float4 w = a4[i]; ag[4*i] = w.x; ag[4*i+1] = w.y; ag[4*i+2] = w.z; ag[4*i+3] = w.w;
    }
    float deg = (float)g_degi[n0];
    float s[H];
#pragma unroll
    for (int j = 0; j < H; j++) s[j] = fmaf(deg, s_c[j], s_b1[j]);
#pragma unroll
    for (int k = 0; k < H; k++) {
        float hv = h[k], av = ag[k];
#pragma unroll
        for (int j = 0; j < H; j++) {
            s[j] = fmaf(hv, sA[k * H + j], s[j]);
            s[j] = fmaf(av, sW[k * H + j], s[j]);
        }
    }
#pragma unroll
    for (int j = 0; j < H; j++) s[j] = fmaxf(s[j], 0.f);
    float o[H];
#pragma unroll
    for (int j = 0; j < H; j++) o[j] = h[j] + s_b2[j];
#pragma unroll
    for (int k = 0; k < H; k++) {
        float tv = s[k];
#pragma unroll
        for (int j = 0; j < H; j++) o[j] = fmaf(tv, sU[k * H + j], o[j]);
    }
    float4* hv = reinterpret_cast<float4*>(g_h + (size_t)n0 * H);
#pragma unroll
    for (int i = 0; i < 8; i++) hv[i] = make_float4(o[4*i], o[4*i+1], o[4*i+2], o[4*i+3]);

    float pa[H];
#pragma unroll
    for (int j = 0; j < H; j++) pa[j] = 0.f;
#pragma unroll
    for (int k = 0; k < H; k++) {
        float hv2 = o[k];
#pragma unroll
        for (int j = 0; j < H; j++) pa[j] = fmaf(hv2, sMA[k * H + j], pa[j]);
    }
    float4* pav = reinterpret_cast<float4*>(g_pa + (size_t)n0 * H);
#pragma unroll
    for (int i = 0; i < 8; i++) pav[i] = make_float4(pa[4*i], pa[4*i+1], pa[4*i+2], pa[4*i+3]);

    float pb[H];
#pragma unroll
    for (int j = 0; j < H; j++) pb[j] = smb1[j];
#pragma unroll
    for (int k = 0; k < H; k++) {
        float hv2 = o[k];
#pragma unroll
        for (int j = 0; j < H; j++) pb[j] = fmaf(hv2, sMB[k * H + j], pb[j]);
    }
    float4* pbv = reinterpret_cast<float4*>(g_pb + (size_t)n0 * H);
#pragma unroll
    for (int i = 0; i < 8; i++) pbv[i] = make_float4(pb[4*i], pb[4*i+1], pb[4*i+2], pb[4*i+3]);
}

// ---------------------------------------------------------------- node update (round 1) + head
__global__ __launch_bounds__(256)
void k_upd_last(const float* __restrict__ uw1, const float* __restrict__ ub1,
                const float* __restrict__ uw2, const float* __restrict__ ub2,
                const float* __restrict__ hw1, const float* __restrict__ hb1,
                const float* __restrict__ hw2, const float* __restrict__ hb2,
                float* __restrict__ out, int n) {
    const int r = 1;
    __shared__ float sA[H * H], sW[H * H], sU[H * H], sHW[H * H];
    __shared__ float s_b1[H], s_b2[H], s_c[H], shb1[H], shw2[H];
    const float* u1a = uw1 + (size_t)r * 2 * H * H;
    int t = threadIdx.x;
    for (int i = t; i < H * H; i += blockDim.x) {
        sA[i]  = u1a[i];
        sW[i]  = g_W[r][i];
        sU[i]  = uw2[(size_t)r * H * H + i];
        sHW[i] = hw1[i];
    }
    if (t < H) {
        s_b1[t] = ub1[(size_t)r * H + t];
        s_b2[t] = ub2[(size_t)r * H + t];
        s_c[t]  = g_c[r][t];
        shb1[t] = hb1[t];
        shw2[t] = hw2[t];
    }
    __syncthreads();
    int n0 = blockIdx.x * blockDim.x + t;
    if (n0 >= n) return;

    float h[H], ag[H];
    const float4* h4 = reinterpret_cast<const float4*>(g_h    + (size_t)n0 * H);
    const float4* a4 = reinterpret_cast<const float4*>(g_aggT + (size_t)n0 * H);
#pragma unroll
    for (int i = 0; i < 8; i++) {
        float4 v = h4[i]; h[4*i] = v.x; h[4*i+1] = v.y; h[4*i+2] = v.z; h[4*i+3] = v.w;
        float4 w = a4[i]; ag[4*i] = w.x; ag[4*i+1] = w.y; ag[4*i+2] = w.z; ag[4*i+3] = w.w;
    }
    float deg = (float)g_degi[n0];
    float s[H];
#pragma unroll
    for (int j = 0; j < H; j++) s[j] = fmaf(deg, s_c[j], s_b1[j]);
#pragma unroll
    for (int k = 0; k < H; k++) {
        float hv = h[k], av = ag[k];
#pragma unroll
        for (int j = 0; j < H; j++) {
            s[j] = fmaf(hv, sA[k * H + j], s[j]);
            s[j] = fmaf(av, sW[k * H + j], s[j]);
        }
    }
#pragma unroll
    for (int j = 0; j < H; j++) s[j] = fmaxf(s[j], 0.f);
    float o[H];
#pragma unroll
    for (int j = 0; j < H; j++) o[j] = h[j] + s_b2[j];
#pragma unroll
    for (int k = 0; k < H; k++) {
        float tv = s[k];
#pragma unroll
        for (int j = 0; j < H; j++) o[j] = fmaf(tv, sU[k * H + j], o[j]);
    }

    float a[H];
#pragma unroll
    for (int j = 0; j < H; j++) a[j] = shb1[j];
#pragma unroll
    for (int k = 0; k < H; k++) {
        float hv2 = o[k];
#pragma unroll
        for (int j = 0; j < H; j++) a[j] = fmaf(hv2, sHW[k * H + j], a[j]);
    }
    float res = hb2[0];
#pragma unroll
    for (int j = 0; j < H; j++) res = fmaf(fmaxf(a[j], 0.f), shw2[j], res);
    out[n0] = res;
}

// ---------------------------------------------------------------- launch
extern "C" void kernel_launch(void* const* d_in, const int* in_sizes, int n_in,
                              void* d_out, int out_size) {
    const float* nf      = (const float*)d_in[0];
    const void*  edges   = d_in[1];
    const float* ef      = (const float*)d_in[2];
    const float* enc_w1  = (const float*)d_in[3];
    const float* enc_b1  = (const float*)d_in[4];
    const float* enc_w2  = (const float*)d_in[5];
    const float* enc_b2  = (const float*)d_in[6];
    const float* msg_w1  = (const float*)d_in[7];
    const float* msg_b1  = (const float*)d_in[8];
    const float* msg_w2  = (const float*)d_in[9];
    const float* msg_b2  = (const float*)d_in[10];
    const float* upd_w1  = (const float*)d_in[11];
    const float* upd_b1  = (const float*)d_in[12];
    const float* upd_w2  = (const float*)d_in[13];
    const float* upd_b2  = (const float*)d_in[14];
    const float* head_w1 = (const float*)d_in[15];
    const float* head_b1 = (const float*)d_in[16];
    const float* head_w2 = (const float*)d_in[17];
    const float* head_b2 = (const float*)d_in[18];

    int n  = in_sizes[0] / 16;  // 100000
    int ne = in_sizes[1] / 2;   // 3200000
    if (n > NN) n = NN;
    if (ne > NE) ne = NE;

    int nb = (n + 255) / 256;
    int eb = (ne + 255) / 256;
    int ab = (n + 15) / 16;             // k_agg: 8 warps x 2 nodes per block

    k_detect<<<1, 32>>>((const int*)edges, ne);
    k_enc<<<nb, 256>>>(nf, enc_w1, enc_b1, enc_w2, enc_b2, msg_w1, msg_b1, n);
    k_deg<<<eb, 256>>>(edges, ne, n);
    k_scan1<<<nb, 256>>>(n);
    k_scan2<<<1, 512>>>(nb);
    k_scan3<<<nb, 256>>>(n);
    k_scatter<<<eb, 256>>>(edges, ef, ne, n);
    k_combine<<<2, dim3(32, 32)>>>(msg_w2, msg_b2, upd_w1);
    k_agg<<<ab, 256>>>(msg_w1, 0, n);
    k_upd_mid<<<nb, 256>>>(upd_w1, upd_b1, upd_w2, upd_b2, msg_w1, msg_b1, n);
    k_agg<<<ab, 256>>>(msg_w1, 1, n);
    k_upd_last<<<nb, 256>>>(upd_w1, upd_b1, upd_w2, upd_b2,
                            head_w1, head_b1, head_w2, head_b2, (float*)d_out, n);
}